// round 16
// baseline (speedup 1.0000x reference)
#include <cuda_runtime.h>
#include <cuda_fp16.h>
#include <cuda_bf16.h>
#include <stdint.h>

#define N_RAYS   4096
#define N_INTERS 1536
#define NSAMP    1535          // N_INTERS - 1
#define RESV     128
#define CHAN     28
#define NVOX     (128*128*128)
#define CHSTRIDE NVOX
#define TR_BLOCKS (NVOX / 256)   // 8192 transpose blocks

__device__ int    g_ray_count[N_RAYS];
__device__ int    g_ray_base[N_RAYS + 1];   // exclusive scan + sentinel nm
// per-sample descriptor: .x = v000 | sx<<21 | sy<<22 | sz<<23 ; .y/.z/.w = fx/fy/fz bits
__device__ uint4  g_mapv[(size_t)N_RAYS * NSAMP];
struct RayPack { float4 o_start; float4 d; };
__device__ RayPack g_raypack[N_RAYS];

// channel-last fp16 grid: voxel record = 28 halves + 4 pad = 64B = 4x uint4
__device__ uint4 g_data64[(size_t)NVOX * 4];

// --- mask-critical math: must be bit-stable under --use_fast_math ---
__device__ __forceinline__ float voxel_len() {
    return __fdiv_rn(__fsqrt_rn(27.0f), 1536.0f);
}

__device__ __forceinline__ float compute_start(float ox, float oy, float oz,
                                               float dx, float dy, float dz) {
    float px = __fdiv_rn(1.5f - ox, dx);
    float py = __fdiv_rn(1.5f - oy, dy);
    float pz = __fdiv_rn(1.5f - oz, dz);
    float nx = __fdiv_rn(-1.5f - ox, dx);
    float ny = __fdiv_rn(-1.5f - oy, dy);
    float nz = __fdiv_rn(-1.5f - oz, dz);
    float ix = fminf(px, nx);
    float iy = fminf(py, ny);
    float iz = fminf(pz, nz);
    float s  = fmaxf(fmaxf(ix, iy), iz);
    return fminf(fmaxf(s, 0.2f), 6.0f);
}

__device__ __forceinline__ float sample_t(float start, int j) {
    return __fadd_rn(start, __fmul_rn((float)j, voxel_len()));
}

__device__ __forceinline__ void point_at(float start, int j,
                                         float ox, float oy, float oz,
                                         float dx, float dy, float dz,
                                         float& px, float& py, float& pz) {
    float t = sample_t(start, j);
    px = __fadd_rn(ox, __fmul_rn(t, dx));
    py = __fadd_rn(oy, __fmul_rn(t, dy));
    pz = __fadd_rn(oz, __fmul_rn(t, dz));
}

__device__ __forceinline__ bool in_box(float px, float py, float pz) {
    return (-1.5f < px) & (px < 1.5f) &
           (-1.5f < py) & (py < 1.5f) &
           (-1.5f < pz) & (pz < 1.5f);
}

// exact mask predicate (bit-identical to the original mask pass)
__device__ __forceinline__ bool pred(float start, int j,
                                     float ox, float oy, float oz,
                                     float dx, float dy, float dz) {
    float px, py, pz;
    point_at(start, j, ox, oy, oz, dx, dy, dz, px, py, pz);
    return in_box(px, py, pz);
}

// ---- packed f32x2 helpers (exact fp32 pair math; FFMA2 in SASS) ----
__device__ __forceinline__ unsigned long long h2f2(unsigned h2bits) {
    __half2 h = *reinterpret_cast<const __half2*>(&h2bits);
    float2 f = __half22float2(h);
    unsigned long long u;
    asm("mov.b64 %0, {%1, %2};" : "=l"(u) : "f"(f.x), "f"(f.y));
    return u;
}
__device__ __forceinline__ unsigned long long bcast2(float w) {
    unsigned long long u;
    asm("mov.b64 %0, {%1, %1};" : "=l"(u) : "f"(w));
    return u;
}
__device__ __forceinline__ unsigned long long mul2(unsigned long long a, unsigned long long b) {
    unsigned long long r;
    asm("mul.rn.f32x2 %0, %1, %2;" : "=l"(r) : "l"(a), "l"(b));
    return r;
}
__device__ __forceinline__ unsigned long long fma2(unsigned long long a, unsigned long long b,
                                                   unsigned long long c) {
    unsigned long long r;
    asm("fma.rn.f32x2 %0, %1, %2, %3;" : "=l"(r) : "l"(a), "l"(b), "l"(c));
    return r;
}
__device__ __forceinline__ float2 unpack2(unsigned long long u) {
    float2 f;
    asm("mov.b64 {%0, %1}, %2;" : "=f"(f.x), "=f"(f.y) : "l"(u));
    return f;
}

// ============ Kernel 0: parallel per-ray start + exact cnt ===========================
__global__ void __launch_bounds__(256)
k_count(const float* __restrict__ rays_o, const float* __restrict__ rays_d) {
    int ray = blockIdx.x * 256 + threadIdx.x;
    if (ray >= N_RAYS) return;

    float ox = rays_o[ray*3+0], oy = rays_o[ray*3+1], oz = rays_o[ray*3+2];
    float dx = rays_d[ray*3+0], dy = rays_d[ray*3+1], dz = rays_d[ray*3+2];
    float start = compute_start(ox, oy, oz, dx, dy, dz);

    RayPack rp;
    rp.o_start = make_float4(ox, oy, oz, start);
    rp.d       = make_float4(dx, dy, dz, 0.0f);
    g_raypack[ray] = rp;

    float te = 1e30f;
    if (dx > 0.0f) te = fminf(te, (1.5f - ox) / dx);
    else if (dx < 0.0f) te = fminf(te, (-1.5f - ox) / dx);
    if (dy > 0.0f) te = fminf(te, (1.5f - oy) / dy);
    else if (dy < 0.0f) te = fminf(te, (-1.5f - oy) / dy);
    if (dz > 0.0f) te = fminf(te, (1.5f - oz) / dz);
    else if (dz < 0.0f) te = fminf(te, (-1.5f - oz) / dz);

    float fj = (te - start) / voxel_len();
    int j = (fj < 0.0f) ? 0 : ((fj > (float)NSAMP) ? NSAMP : (int)fj);
    while (j > 0 && !pred(start, j - 1, ox, oy, oz, dx, dy, dz)) j--;
    while (j < NSAMP && pred(start, j, ox, oy, oz, dx, dy, dz)) j++;
    g_ray_count[ray] = j;
}

// ============ Kernel 1: exclusive scan over 4096 ray counts ==========================
__global__ void __launch_bounds__(1024)
k_scan() {
    __shared__ int sh[1024];
    int tid = threadIdx.x;
    int c0 = g_ray_count[tid*4+0];
    int c1 = g_ray_count[tid*4+1];
    int c2 = g_ray_count[tid*4+2];
    int c3 = g_ray_count[tid*4+3];
    int tot = c0 + c1 + c2 + c3;
    sh[tid] = tot;
    __syncthreads();
    for (int off = 1; off < 1024; off <<= 1) {
        int v = (tid >= off) ? sh[tid - off] : 0;
        __syncthreads();
        sh[tid] += v;
        __syncthreads();
    }
    int excl = sh[tid] - tot;
    g_ray_base[tid*4+0] = excl;
    g_ray_base[tid*4+1] = excl + c0;
    g_ray_base[tid*4+2] = excl + c0 + c1;
    g_ray_base[tid*4+3] = excl + c0 + c1 + c2;
    if (tid == 1023) g_ray_base[N_RAYS] = sh[1023];   // sentinel = nm
}

// ============ Kernel 2 (fused): transpose->fp16  +  descriptor map + sub_pts ========
__global__ void __launch_bounds__(256)
k_trmap(const float* __restrict__ data, float* __restrict__ sub_out) {
    int tid = threadIdx.x;

    if (blockIdx.x < TR_BLOCKS) {
        __shared__ float tile[28][257];
        int v0 = blockIdx.x * 256;
        #pragma unroll
        for (int c = 0; c < 28; c++)
            tile[c][tid] = __ldg(data + (size_t)c * CHSTRIDE + v0 + tid);
        __syncthreads();
        uint2* out = (uint2*)g_data64;   // 8 uint2 per voxel, write all 8 (full 64B lines)
        #pragma unroll
        for (int k = 0; k < 8; k++) {
            int l  = k * 256 + tid;
            int v  = l >> 3;
            int c4 = l & 7;
            uint2 u;
            if (c4 < 7) {
                __half2 h0 = __floats2half2_rn(tile[4*c4+0][v], tile[4*c4+1][v]);
                __half2 h1 = __floats2half2_rn(tile[4*c4+2][v], tile[4*c4+3][v]);
                u.x = *reinterpret_cast<unsigned*>(&h0);
                u.y = *reinterpret_cast<unsigned*>(&h1);
            } else {
                u.x = 0u; u.y = 0u;
            }
            out[(size_t)(v0 + v) * 8 + c4] = u;
        }
        return;
    }

    // ---- descriptor-map path: one ray per block ----
    int ray  = blockIdx.x - TR_BLOCKS;
    int base = __ldg(&g_ray_base[ray]);
    int cnt  = __ldg(&g_ray_base[ray + 1]) - base;
    float4 osr = __ldg(&g_raypack[ray].o_start);
    float4 dd  = __ldg(&g_raypack[ray].d);

    const float INV = 0.66666668653f;  // float(2/3)

    for (int j = tid; j < cnt; j += 256) {
        float px, py, pz;
        point_at(osr.w, j, osr.x, osr.y, osr.z, dd.x, dd.y, dd.z, px, py, pz);
        float nx = (px + 1.5f) * INV - 1.0f;
        float ny = (py + 1.5f) * INV - 1.0f;
        float nz = (pz + 1.5f) * INV - 1.0f;

        int s = base + j;

        // sub_pts (same formulas as before)
        float gx = (nx + 1.0f) * 64.0f;
        float gy = (ny + 1.0f) * 64.0f;
        float gz = (nz + 1.0f) * 64.0f;
        float gix = fminf(fmaxf(floorf(gx), 0.0f), 127.0f);
        float giy = fminf(fmaxf(floorf(gy), 0.0f), 127.0f);
        float giz = fminf(fmaxf(floorf(gz), 0.0f), 127.0f);
        __stcs(sub_out + (size_t)s*3+0, gx - gix);
        __stcs(sub_out + (size_t)s*3+1, gy - giy);
        __stcs(sub_out + (size_t)s*3+2, gz - giz);

        // trilinear descriptor (same formulas as before)
        float x = (nx + 1.0f) * 63.5f;
        float y = (ny + 1.0f) * 63.5f;
        float z = (nz + 1.0f) * 63.5f;
        float x0f = floorf(x), y0f = floorf(y), z0f = floorf(z);
        float fx = x - x0f, fy = y - y0f, fz = z - z0f;
        int ix0 = min(max((int)x0f, 0), 127);
        int iy0 = min(max((int)y0f, 0), 127);
        int iz0 = min(max((int)z0f, 0), 127);
        int sx = (ix0 < 127) ? 1 : 0;
        int sy = (iy0 < 127) ? 1 : 0;
        int sz = (iz0 < 127) ? 1 : 0;

        uint4 ent;
        ent.x = (unsigned)((iz0 * RESV + iy0) * RESV + ix0)
              | ((unsigned)sx << 21) | ((unsigned)sy << 22) | ((unsigned)sz << 23);
        ent.y = __float_as_uint(fx);
        ent.z = __float_as_uint(fy);
        ent.w = __float_as_uint(fz);
        g_mapv[s] = ent;
    }
}

// ============ Kernel 3 (fused): mask/intersections blocks + flat gather ==============
__global__ void __launch_bounds__(256)
k_gather(float* __restrict__ data_out,
         float* __restrict__ mask_out, float* __restrict__ intr_out, int nm) {
    int tid = threadIdx.x;

    if (blockIdx.x < N_RAYS) {
        int ray  = blockIdx.x;
        int base = __ldg(&g_ray_base[ray]);
        int cnt  = __ldg(&g_ray_base[ray + 1]) - base;
        float start = __ldg(&g_raypack[ray].o_start).w;
        for (int j = tid; j < N_INTERS; j += 256)
            __stcs(intr_out + (size_t)ray * N_INTERS + j, sample_t(start, j));
        for (int j = tid; j < NSAMP; j += 256)
            __stcs(mask_out + (size_t)ray * NSAMP + j, (j < cnt) ? 1.0f : 0.0f);
        return;
    }

    // -------- flat gather: 4 lanes per sample, precomputed descriptor, f32x2 math ----
    int gt = (blockIdx.x - N_RAYS) * 256 + tid;
    int s   = gt >> 2;
    int sub = gt & 3;
    if (s >= nm) return;

    uint4 ent = __ldg(&g_mapv[s]);
    int v000 = ent.x & 0x1FFFFF;
    int vx   = (ent.x >> 21) & 1;          // +1 in x (or 0 at edge)
    int vy   = ((ent.x >> 22) & 1) << 7;   // +128 in y
    int vz   = ((ent.x >> 23) & 1) << 14;  // +16384 in z
    float fx = __uint_as_float(ent.y);
    float fy = __uint_as_float(ent.z);
    float fz = __uint_as_float(ent.w);

    float gxc = 1.0f - fx, gyc = 1.0f - fy, gzc = 1.0f - fz;
    unsigned long long w0 = bcast2(gzc * gyc * gxc);
    unsigned long long w1 = bcast2(gzc * gyc * fx);
    unsigned long long w2 = bcast2(gzc * fy  * gxc);
    unsigned long long w3 = bcast2(gzc * fy  * fx);
    unsigned long long w4 = bcast2(fz  * gyc * gxc);
    unsigned long long w5 = bcast2(fz  * gyc * fx);
    unsigned long long w6 = bcast2(fz  * fy  * gxc);
    unsigned long long w7 = bcast2(fz  * fy  * fx);

    const uint4* G = g_data64;
    uint4 a = __ldg(G + (((size_t)(v000          )) << 2) + sub);
    uint4 b = __ldg(G + (((size_t)(v000 + vx     )) << 2) + sub);
    uint4 c = __ldg(G + (((size_t)(v000 + vy     )) << 2) + sub);
    uint4 d = __ldg(G + (((size_t)(v000 + vy + vx)) << 2) + sub);
    uint4 e = __ldg(G + (((size_t)(v000 + vz     )) << 2) + sub);
    uint4 f = __ldg(G + (((size_t)(v000 + vz + vx)) << 2) + sub);
    uint4 h = __ldg(G + (((size_t)(v000 + vz + vy)) << 2) + sub);
    uint4 i = __ldg(G + (((size_t)(v000 + vz + vy + vx)) << 2) + sub);

    // four packed accumulators, each = weighted sum of 8 corners (exact fp32 pairs)
    unsigned long long acc0, acc1, acc2, acc3;
    acc0 = mul2(w0, h2f2(a.x));
    acc1 = mul2(w0, h2f2(a.y));
    acc2 = mul2(w0, h2f2(a.z));
    acc3 = mul2(w0, h2f2(a.w));
    acc0 = fma2(w1, h2f2(b.x), acc0);
    acc1 = fma2(w1, h2f2(b.y), acc1);
    acc2 = fma2(w1, h2f2(b.z), acc2);
    acc3 = fma2(w1, h2f2(b.w), acc3);
    acc0 = fma2(w2, h2f2(c.x), acc0);
    acc1 = fma2(w2, h2f2(c.y), acc1);
    acc2 = fma2(w2, h2f2(c.z), acc2);
    acc3 = fma2(w2, h2f2(c.w), acc3);
    acc0 = fma2(w3, h2f2(d.x), acc0);
    acc1 = fma2(w3, h2f2(d.y), acc1);
    acc2 = fma2(w3, h2f2(d.z), acc2);
    acc3 = fma2(w3, h2f2(d.w), acc3);
    acc0 = fma2(w4, h2f2(e.x), acc0);
    acc1 = fma2(w4, h2f2(e.y), acc1);
    acc2 = fma2(w4, h2f2(e.z), acc2);
    acc3 = fma2(w4, h2f2(e.w), acc3);
    acc0 = fma2(w5, h2f2(f.x), acc0);
    acc1 = fma2(w5, h2f2(f.y), acc1);
    acc2 = fma2(w5, h2f2(f.z), acc2);
    acc3 = fma2(w5, h2f2(f.w), acc3);
    acc0 = fma2(w6, h2f2(h.x), acc0);
    acc1 = fma2(w6, h2f2(h.y), acc1);
    acc2 = fma2(w6, h2f2(h.z), acc2);
    acc3 = fma2(w6, h2f2(h.w), acc3);
    acc0 = fma2(w7, h2f2(i.x), acc0);
    acc1 = fma2(w7, h2f2(i.y), acc1);
    acc2 = fma2(w7, h2f2(i.z), acc2);
    acc3 = fma2(w7, h2f2(i.w), acc3);

    float2 r01 = unpack2(acc0);
    float2 r23 = unpack2(acc1);
    float2 r45 = unpack2(acc2);
    float2 r67 = unpack2(acc3);

    float4* op = (float4*)(data_out + (size_t)s * CHAN);
    __stcs(op + sub*2, make_float4(r01.x, r01.y, r23.x, r23.y));
    if (sub < 3)
        __stcs(op + sub*2 + 1, make_float4(r45.x, r45.y, r67.x, r67.y));
}

extern "C" void kernel_launch(void* const* d_in, const int* in_sizes, int n_in,
                              void* d_out, int out_size) {
    const float* rays_o = (const float*)d_in[0];
    const float* rays_d = (const float*)d_in[1];
    const float* data   = (const float*)d_in[2];
    float* out = (float*)d_out;

    const long long MASK_N = (long long)N_RAYS * NSAMP;    // 6,287,360
    const long long INTR_N = (long long)N_RAYS * N_INTERS; // 6,291,456
    long long nm = ((long long)out_size - MASK_N - INTR_N) / 31LL;

    float* data_out = out;
    float* mask_out = out + nm * CHAN;
    float* intr_out = mask_out + MASK_N;
    float* sub_out  = intr_out + INTR_N;

    k_count<<<N_RAYS / 256, 256>>>(rays_o, rays_d);
    k_scan<<<1, 1024>>>();
    k_trmap<<<TR_BLOCKS + N_RAYS, 256>>>(data, sub_out);

    long long nthreads = nm * 4;
    int nb_g = (int)((nthreads + 255) / 256);
    k_gather<<<N_RAYS + nb_g, 256>>>(data_out, mask_out, intr_out, (int)nm);
}

// round 17
// speedup vs baseline: 1.0768x; 1.0768x over previous
#include <cuda_runtime.h>
#include <cuda_fp16.h>
#include <cuda_bf16.h>
#include <stdint.h>

#define N_RAYS   4096
#define N_INTERS 1536
#define NSAMP    1535          // N_INTERS - 1
#define RESV     128
#define CHAN     28
#define NVOX     (128*128*128)
#define CHSTRIDE NVOX
#define TR_BLOCKS (NVOX / 256)   // 8192 transpose blocks

__device__ int    g_ray_count[N_RAYS];
__device__ int    g_ray_base[N_RAYS + 1];   // exclusive scan + sentinel nm
// per-sample descriptor: .x = v000 | sx<<21 | sy<<22 | sz<<23 ; .y/.z/.w = fx/fy/fz bits
__device__ uint4  g_mapv[(size_t)N_RAYS * NSAMP];
struct RayPack { float4 o_start; float4 d; };
__device__ RayPack g_raypack[N_RAYS];

// channel-last fp16 grid: voxel record = 28 halves + 4 pad = 64B = 4x uint4
__device__ uint4 g_data64[(size_t)NVOX * 4];

// --- mask-critical math: must be bit-stable under --use_fast_math ---
__device__ __forceinline__ float voxel_len() {
    return __fdiv_rn(__fsqrt_rn(27.0f), 1536.0f);
}

__device__ __forceinline__ float compute_start(float ox, float oy, float oz,
                                               float dx, float dy, float dz) {
    float px = __fdiv_rn(1.5f - ox, dx);
    float py = __fdiv_rn(1.5f - oy, dy);
    float pz = __fdiv_rn(1.5f - oz, dz);
    float nx = __fdiv_rn(-1.5f - ox, dx);
    float ny = __fdiv_rn(-1.5f - oy, dy);
    float nz = __fdiv_rn(-1.5f - oz, dz);
    float ix = fminf(px, nx);
    float iy = fminf(py, ny);
    float iz = fminf(pz, nz);
    float s  = fmaxf(fmaxf(ix, iy), iz);
    return fminf(fmaxf(s, 0.2f), 6.0f);
}

__device__ __forceinline__ float sample_t(float start, int j) {
    return __fadd_rn(start, __fmul_rn((float)j, voxel_len()));
}

__device__ __forceinline__ void point_at(float start, int j,
                                         float ox, float oy, float oz,
                                         float dx, float dy, float dz,
                                         float& px, float& py, float& pz) {
    float t = sample_t(start, j);
    px = __fadd_rn(ox, __fmul_rn(t, dx));
    py = __fadd_rn(oy, __fmul_rn(t, dy));
    pz = __fadd_rn(oz, __fmul_rn(t, dz));
}

__device__ __forceinline__ bool in_box(float px, float py, float pz) {
    return (-1.5f < px) & (px < 1.5f) &
           (-1.5f < py) & (py < 1.5f) &
           (-1.5f < pz) & (pz < 1.5f);
}

// exact mask predicate (bit-identical to the original mask pass)
__device__ __forceinline__ bool pred(float start, int j,
                                     float ox, float oy, float oz,
                                     float dx, float dy, float dz) {
    float px, py, pz;
    point_at(start, j, ox, oy, oz, dx, dy, dz, px, py, pz);
    return in_box(px, py, pz);
}

// unpack 8 halves (uint4) into 8 floats
__device__ __forceinline__ void unpack8(uint4 u, float* f) {
    float2 t;
    t = __half22float2(*reinterpret_cast<__half2*>(&u.x)); f[0]=t.x; f[1]=t.y;
    t = __half22float2(*reinterpret_cast<__half2*>(&u.y)); f[2]=t.x; f[3]=t.y;
    t = __half22float2(*reinterpret_cast<__half2*>(&u.z)); f[4]=t.x; f[5]=t.y;
    t = __half22float2(*reinterpret_cast<__half2*>(&u.w)); f[6]=t.x; f[7]=t.y;
}

// ============ Kernel 0: parallel per-ray start + exact cnt ===========================
__global__ void __launch_bounds__(256)
k_count(const float* __restrict__ rays_o, const float* __restrict__ rays_d) {
    int ray = blockIdx.x * 256 + threadIdx.x;
    if (ray >= N_RAYS) return;

    float ox = rays_o[ray*3+0], oy = rays_o[ray*3+1], oz = rays_o[ray*3+2];
    float dx = rays_d[ray*3+0], dy = rays_d[ray*3+1], dz = rays_d[ray*3+2];
    float start = compute_start(ox, oy, oz, dx, dy, dz);

    RayPack rp;
    rp.o_start = make_float4(ox, oy, oz, start);
    rp.d       = make_float4(dx, dy, dz, 0.0f);
    g_raypack[ray] = rp;

    float te = 1e30f;
    if (dx > 0.0f) te = fminf(te, (1.5f - ox) / dx);
    else if (dx < 0.0f) te = fminf(te, (-1.5f - ox) / dx);
    if (dy > 0.0f) te = fminf(te, (1.5f - oy) / dy);
    else if (dy < 0.0f) te = fminf(te, (-1.5f - oy) / dy);
    if (dz > 0.0f) te = fminf(te, (1.5f - oz) / dz);
    else if (dz < 0.0f) te = fminf(te, (-1.5f - oz) / dz);

    float fj = (te - start) / voxel_len();
    int j = (fj < 0.0f) ? 0 : ((fj > (float)NSAMP) ? NSAMP : (int)fj);
    while (j > 0 && !pred(start, j - 1, ox, oy, oz, dx, dy, dz)) j--;
    while (j < NSAMP && pred(start, j, ox, oy, oz, dx, dy, dz)) j++;
    g_ray_count[ray] = j;
}

// ============ Kernel 1: exclusive scan over 4096 ray counts ==========================
__global__ void __launch_bounds__(1024)
k_scan() {
    __shared__ int sh[1024];
    int tid = threadIdx.x;
    int c0 = g_ray_count[tid*4+0];
    int c1 = g_ray_count[tid*4+1];
    int c2 = g_ray_count[tid*4+2];
    int c3 = g_ray_count[tid*4+3];
    int tot = c0 + c1 + c2 + c3;
    sh[tid] = tot;
    __syncthreads();
    for (int off = 1; off < 1024; off <<= 1) {
        int v = (tid >= off) ? sh[tid - off] : 0;
        __syncthreads();
        sh[tid] += v;
        __syncthreads();
    }
    int excl = sh[tid] - tot;
    g_ray_base[tid*4+0] = excl;
    g_ray_base[tid*4+1] = excl + c0;
    g_ray_base[tid*4+2] = excl + c0 + c1;
    g_ray_base[tid*4+3] = excl + c0 + c1 + c2;
    if (tid == 1023) g_ray_base[N_RAYS] = sh[1023];   // sentinel = nm
}

// ============ Kernel 2 (fused): transpose->fp16  +  descriptor map + sub_pts ========
__global__ void __launch_bounds__(256)
k_trmap(const float* __restrict__ data, float* __restrict__ sub_out) {
    int tid = threadIdx.x;

    if (blockIdx.x < TR_BLOCKS) {
        __shared__ float tile[28][257];
        int v0 = blockIdx.x * 256;
        #pragma unroll
        for (int c = 0; c < 28; c++)
            tile[c][tid] = __ldg(data + (size_t)c * CHSTRIDE + v0 + tid);
        __syncthreads();
        uint2* out = (uint2*)g_data64;   // 8 uint2 per voxel, write all 8 (full 64B lines)
        #pragma unroll
        for (int k = 0; k < 8; k++) {
            int l  = k * 256 + tid;
            int v  = l >> 3;
            int c4 = l & 7;
            uint2 u;
            if (c4 < 7) {
                __half2 h0 = __floats2half2_rn(tile[4*c4+0][v], tile[4*c4+1][v]);
                __half2 h1 = __floats2half2_rn(tile[4*c4+2][v], tile[4*c4+3][v]);
                u.x = *reinterpret_cast<unsigned*>(&h0);
                u.y = *reinterpret_cast<unsigned*>(&h1);
            } else {
                u.x = 0u; u.y = 0u;
            }
            out[(size_t)(v0 + v) * 8 + c4] = u;
        }
        return;
    }

    // ---- descriptor-map path: one ray per block ----
    int ray  = blockIdx.x - TR_BLOCKS;
    int base = __ldg(&g_ray_base[ray]);
    int cnt  = __ldg(&g_ray_base[ray + 1]) - base;
    float4 osr = __ldg(&g_raypack[ray].o_start);
    float4 dd  = __ldg(&g_raypack[ray].d);

    const float INV = 0.66666668653f;  // float(2/3)

    for (int j = tid; j < cnt; j += 256) {
        float px, py, pz;
        point_at(osr.w, j, osr.x, osr.y, osr.z, dd.x, dd.y, dd.z, px, py, pz);
        float nx = (px + 1.5f) * INV - 1.0f;
        float ny = (py + 1.5f) * INV - 1.0f;
        float nz = (pz + 1.5f) * INV - 1.0f;

        int s = base + j;

        // sub_pts (same formulas as before)
        float gx = (nx + 1.0f) * 64.0f;
        float gy = (ny + 1.0f) * 64.0f;
        float gz = (nz + 1.0f) * 64.0f;
        float gix = fminf(fmaxf(floorf(gx), 0.0f), 127.0f);
        float giy = fminf(fmaxf(floorf(gy), 0.0f), 127.0f);
        float giz = fminf(fmaxf(floorf(gz), 0.0f), 127.0f);
        __stcs(sub_out + (size_t)s*3+0, gx - gix);
        __stcs(sub_out + (size_t)s*3+1, gy - giy);
        __stcs(sub_out + (size_t)s*3+2, gz - giz);

        // trilinear descriptor (same formulas as before)
        float x = (nx + 1.0f) * 63.5f;
        float y = (ny + 1.0f) * 63.5f;
        float z = (nz + 1.0f) * 63.5f;
        float x0f = floorf(x), y0f = floorf(y), z0f = floorf(z);
        float fx = x - x0f, fy = y - y0f, fz = z - z0f;
        int ix0 = min(max((int)x0f, 0), 127);
        int iy0 = min(max((int)y0f, 0), 127);
        int iz0 = min(max((int)z0f, 0), 127);
        int sx = (ix0 < 127) ? 1 : 0;
        int sy = (iy0 < 127) ? 1 : 0;
        int sz = (iz0 < 127) ? 1 : 0;

        uint4 ent;
        ent.x = (unsigned)((iz0 * RESV + iy0) * RESV + ix0)
              | ((unsigned)sx << 21) | ((unsigned)sy << 22) | ((unsigned)sz << 23);
        ent.y = __float_as_uint(fx);
        ent.z = __float_as_uint(fy);
        ent.w = __float_as_uint(fz);
        __stcs(&g_mapv[s], ent);    // evict-first: read exactly once by gather
    }
}

// ============ Kernel 3 (fused): mask/intersections blocks + flat gather ==============
__global__ void __launch_bounds__(256)
k_gather(float* __restrict__ data_out,
         float* __restrict__ mask_out, float* __restrict__ intr_out, int nm) {
    int tid = threadIdx.x;

    if (blockIdx.x < N_RAYS) {
        int ray  = blockIdx.x;
        int base = __ldg(&g_ray_base[ray]);
        int cnt  = __ldg(&g_ray_base[ray + 1]) - base;
        float start = __ldg(&g_raypack[ray].o_start).w;
        // intersections: vectorized (rows are 16B-aligned, 384 float4 per row)
        float4* irow = (float4*)(intr_out + (size_t)ray * N_INTERS);
        for (int q = tid; q < N_INTERS / 4; q += 256) {
            int j = q * 4;
            float4 v = make_float4(sample_t(start, j),     sample_t(start, j + 1),
                                   sample_t(start, j + 2), sample_t(start, j + 3));
            __stcs(irow + q, v);
        }
        for (int j = tid; j < NSAMP; j += 256)
            __stcs(mask_out + (size_t)ray * NSAMP + j, (j < cnt) ? 1.0f : 0.0f);
        return;
    }

    // -------- flat gather: 4 lanes per sample, precomputed descriptor --------
    int gt = (blockIdx.x - N_RAYS) * 256 + tid;
    int s   = gt >> 2;
    int sub = gt & 3;
    if (s >= nm) return;

    uint4 ent = __ldcs(&g_mapv[s]);   // evict-first streaming read
    int v000 = ent.x & 0x1FFFFF;
    int vx   = (ent.x >> 21) & 1;          // +1 in x (or 0 at edge)
    int vy   = ((ent.x >> 22) & 1) << 7;   // +128 in y
    int vz   = ((ent.x >> 23) & 1) << 14;  // +16384 in z
    float fx = __uint_as_float(ent.y);
    float fy = __uint_as_float(ent.z);
    float fz = __uint_as_float(ent.w);

    float gxc = 1.0f - fx, gyc = 1.0f - fy, gzc = 1.0f - fz;
    float w000 = gzc * gyc * gxc;
    float w001 = gzc * gyc * fx;
    float w010 = gzc * fy  * gxc;
    float w011 = gzc * fy  * fx;
    float w100 = fz  * gyc * gxc;
    float w101 = fz  * gyc * fx;
    float w110 = fz  * fy  * gxc;
    float w111 = fz  * fy  * fx;

    const uint4* G = g_data64;
    uint4 a = __ldg(G + (((size_t)(v000          )) << 2) + sub);
    uint4 b = __ldg(G + (((size_t)(v000 + vx     )) << 2) + sub);
    uint4 c = __ldg(G + (((size_t)(v000 + vy     )) << 2) + sub);
    uint4 d = __ldg(G + (((size_t)(v000 + vy + vx)) << 2) + sub);
    uint4 e = __ldg(G + (((size_t)(v000 + vz     )) << 2) + sub);
    uint4 f = __ldg(G + (((size_t)(v000 + vz + vx)) << 2) + sub);
    uint4 h = __ldg(G + (((size_t)(v000 + vz + vy)) << 2) + sub);
    uint4 i = __ldg(G + (((size_t)(v000 + vz + vy + vx)) << 2) + sub);

    float fa[8], fb[8], fc[8], fd[8], fe[8], ff[8], fh[8], fi[8];
    unpack8(a, fa); unpack8(b, fb); unpack8(c, fc); unpack8(d, fd);
    unpack8(e, fe); unpack8(f, ff); unpack8(h, fh); unpack8(i, fi);

    float r[8];
    #pragma unroll
    for (int k = 0; k < 8; k++) {
        r[k] = w000*fa[k] + w001*fb[k] + w010*fc[k] + w011*fd[k]
             + w100*fe[k] + w101*ff[k] + w110*fh[k] + w111*fi[k];
    }

    float4* op = (float4*)(data_out + (size_t)s * CHAN);
    __stcs(op + sub*2, make_float4(r[0], r[1], r[2], r[3]));
    if (sub < 3)
        __stcs(op + sub*2 + 1, make_float4(r[4], r[5], r[6], r[7]));
}

extern "C" void kernel_launch(void* const* d_in, const int* in_sizes, int n_in,
                              void* d_out, int out_size) {
    const float* rays_o = (const float*)d_in[0];
    const float* rays_d = (const float*)d_in[1];
    const float* data   = (const float*)d_in[2];
    float* out = (float*)d_out;

    const long long MASK_N = (long long)N_RAYS * NSAMP;    // 6,287,360
    const long long INTR_N = (long long)N_RAYS * N_INTERS; // 6,291,456
    long long nm = ((long long)out_size - MASK_N - INTR_N) / 31LL;

    float* data_out = out;
    float* mask_out = out + nm * CHAN;
    float* intr_out = mask_out + MASK_N;
    float* sub_out  = intr_out + INTR_N;

    k_count<<<N_RAYS / 256, 256>>>(rays_o, rays_d);
    k_scan<<<1, 1024>>>();
    k_trmap<<<TR_BLOCKS + N_RAYS, 256>>>(data, sub_out);

    long long nthreads = nm * 4;
    int nb_g = (int)((nthreads + 255) / 256);
    k_gather<<<N_RAYS + nb_g, 256>>>(data_out, mask_out, intr_out, (int)nm);
}